// round 1
// baseline (speedup 1.0000x reference)
#include <cuda_runtime.h>
#include <cstdint>

#define NN 100000
#define DD 128
#define EE 1600000
#define RR 4

// ---------------- device scratch (static: no allocations allowed) ----------
__device__ float g_hs[(size_t)NN * DD];   // per-relation transformed features
__device__ float g_h1[(size_t)NN * DD];   // layer-1 output
__device__ float g_acc[(size_t)NN * DD];  // aggregation accumulator
__device__ float g_dout[RR * NN];         // out-degree counts
__device__ float g_din[RR * NN];          // in-degree counts
__device__ float g_rdout[RR * NN];        // rsqrt(max(deg_out,1))
__device__ float g_rdin[RR * NN];         // rsqrt(max(deg_in,1))

// ---------------- kernels --------------------------------------------------

__global__ void zero_deg_kernel() {
    int i = blockIdx.x * blockDim.x + threadIdx.x;
    if (i < RR * NN) { g_dout[i] = 0.f; g_din[i] = 0.f; }
}

__global__ void zero_acc_kernel() {
    int i = blockIdx.x * blockDim.x + threadIdx.x;
    if (i < NN * DD) g_acc[i] = 0.f;
}

__global__ void deg_kernel(const int* __restrict__ src, const int* __restrict__ dst) {
    long long i = (long long)blockIdx.x * blockDim.x + threadIdx.x;
    if (i >= (long long)RR * EE) return;
    int r = (int)(i / EE);
    atomicAdd(&g_dout[r * NN + src[i]], 1.f);
    atomicAdd(&g_din[r * NN + dst[i]], 1.f);
}

__global__ void rsqrt_kernel() {
    int i = blockIdx.x * blockDim.x + threadIdx.x;
    if (i >= RR * NN) return;
    g_rdout[i] = rsqrtf(fmaxf(g_dout[i], 1.f));
    g_rdin[i]  = rsqrtf(fmaxf(g_din[i], 1.f));
}

// hs[n][j] = sum_k (h[n][k] * rdout[n]) * W[k][j]
// Block: 64 rows x full 128 cols. 256 threads (16x16), 4x8 outputs each.
__global__ __launch_bounds__(256) void gemm_scaled_kernel(
    const float* __restrict__ h, const float* __restrict__ W, int r)
{
    __shared__ float sW[32][DD];   // [k][j]
    __shared__ float sH[64][33];   // [row][k], padded

    const float* rd = &g_rdout[r * NN];
    int tx = threadIdx.x & 15;
    int ty = threadIdx.x >> 4;
    int row0 = blockIdx.x * 64;

    float acc[4][8];
#pragma unroll
    for (int i = 0; i < 4; i++)
#pragma unroll
        for (int j = 0; j < 8; j++) acc[i][j] = 0.f;

    for (int kc = 0; kc < DD; kc += 32) {
        // stage W chunk [32 x 128]
        for (int t = threadIdx.x; t < 32 * DD; t += 256)
            sW[t >> 7][t & 127] = W[(kc + (t >> 7)) * DD + (t & 127)];
        // stage scaled-h chunk [64 x 32]
        for (int t = threadIdx.x; t < 64 * 32; t += 256) {
            int rr = t >> 5, kk = t & 31;
            int n = row0 + rr;
            float v = 0.f;
            if (n < NN) v = h[(size_t)n * DD + kc + kk] * rd[n];
            sH[rr][kk] = v;
        }
        __syncthreads();
#pragma unroll
        for (int k = 0; k < 32; k++) {
            float a[4];
#pragma unroll
            for (int i = 0; i < 4; i++) a[i] = sH[ty * 4 + i][k];
            float4 b0 = *(const float4*)&sW[k][tx * 8];
            float4 b1 = *(const float4*)&sW[k][tx * 8 + 4];
#pragma unroll
            for (int i = 0; i < 4; i++) {
                acc[i][0] += a[i] * b0.x;  acc[i][1] += a[i] * b0.y;
                acc[i][2] += a[i] * b0.z;  acc[i][3] += a[i] * b0.w;
                acc[i][4] += a[i] * b1.x;  acc[i][5] += a[i] * b1.y;
                acc[i][6] += a[i] * b1.z;  acc[i][7] += a[i] * b1.w;
            }
        }
        __syncthreads();
    }
#pragma unroll
    for (int i = 0; i < 4; i++) {
        int row = row0 + ty * 4 + i;
        if (row < NN) {
            float4 v0 = make_float4(acc[i][0], acc[i][1], acc[i][2], acc[i][3]);
            float4 v1 = make_float4(acc[i][4], acc[i][5], acc[i][6], acc[i][7]);
            *(float4*)&g_hs[(size_t)row * DD + tx * 8]     = v0;
            *(float4*)&g_hs[(size_t)row * DD + tx * 8 + 4] = v1;
        }
    }
}

// One warp per edge: acc[dst] += hs[src] * ew * rsqrt(deg_in[dst])
__global__ __launch_bounds__(256) void scatter_kernel(
    const int* __restrict__ src, const int* __restrict__ dst,
    const float* __restrict__ ew, int r)
{
    long long gid = (long long)blockIdx.x * blockDim.x + threadIdx.x;
    int e = (int)(gid >> 5);
    int lane = (int)(gid & 31);
    if (e >= EE) return;
    int s = src[e];
    int d = dst[e];
    float w = ew[e] * g_rdin[r * NN + d];
    float4 v = *(const float4*)(g_hs + (size_t)s * DD + lane * 4);
    float* p = g_acc + (size_t)d * DD + lane * 4;
    asm volatile("red.global.add.v4.f32 [%0], {%1,%2,%3,%4};"
                 :: "l"(p), "f"(v.x * w), "f"(v.y * w), "f"(v.z * w), "f"(v.w * w)
                 : "memory");
}

// out[n][j] = relu(acc[n][j] + sum_r b[r][j])
__global__ void bias_relu_kernel(const float* __restrict__ b, float* __restrict__ out) {
    int i = blockIdx.x * blockDim.x + threadIdx.x;
    if (i >= NN * DD) return;
    int j = i & (DD - 1);
    float bs = b[j] + b[DD + j] + b[2 * DD + j] + b[3 * DD + j];
    out[i] = fmaxf(g_acc[i] + bs, 0.f);
}

// ---------------- launch ----------------------------------------------------

extern "C" void kernel_launch(void* const* d_in, const int* in_sizes, int n_in,
                              void* d_out, int out_size)
{
    const float* x   = (const float*)d_in[0];   // [N, D]
    const int*   src = (const int*)d_in[1];     // [R, E]
    const int*   dst = (const int*)d_in[2];     // [R, E]
    const float* ew  = (const float*)d_in[3];   // [R, E]
    const float* W1  = (const float*)d_in[4];   // [R, D, D]
    const float* b1  = (const float*)d_in[5];   // [R, D]
    const float* W2  = (const float*)d_in[6];   // [R, D, D]
    const float* b2  = (const float*)d_in[7];   // [R, D]
    float* out = (float*)d_out;

    const int T = 256;

    // degrees (shared by both layers)
    zero_deg_kernel<<<(RR * NN + T - 1) / T, T>>>();
    deg_kernel<<<((long long)RR * EE + T - 1) / T, T>>>(src, dst);
    rsqrt_kernel<<<(RR * NN + T - 1) / T, T>>>();

    const int gemm_blocks = (NN + 63) / 64;
    const int scat_blocks = (int)(((long long)EE * 32 + T - 1) / T);
    const int elem_blocks = (NN * DD + T - 1) / T;

    // ---- layer 1 ----
    zero_acc_kernel<<<elem_blocks, T>>>();
    for (int r = 0; r < RR; r++) {
        gemm_scaled_kernel<<<gemm_blocks, T>>>(x, W1 + (size_t)r * DD * DD, r);
        scatter_kernel<<<scat_blocks, T>>>(src + (size_t)r * EE, dst + (size_t)r * EE,
                                           ew + (size_t)r * EE, r);
    }
    bias_relu_kernel<<<elem_blocks, T>>>(b1, g_h1);

    // ---- layer 2 ----
    zero_acc_kernel<<<elem_blocks, T>>>();
    for (int r = 0; r < RR; r++) {
        gemm_scaled_kernel<<<gemm_blocks, T>>>(g_h1, W2 + (size_t)r * DD * DD, r);
        scatter_kernel<<<scat_blocks, T>>>(src + (size_t)r * EE, dst + (size_t)r * EE,
                                           ew + (size_t)r * EE, r);
    }
    bias_relu_kernel<<<elem_blocks, T>>>(b2, out);
}

// round 2
// speedup vs baseline: 1.0353x; 1.0353x over previous
#include <cuda_runtime.h>
#include <mma.h>
#include <cstdint>

using namespace nvcuda;

#define NN 100000
#define NP 100032            // padded to multiple of 64
#define DD 128
#define EE 1600000
#define RR 4

// ---------------- device scratch (static: no allocations allowed) ----------
__device__ float g_Y[(size_t)RR * NP * DD];   // per-relation transformed feats
__device__ float g_h1[(size_t)NN * DD];       // layer-1 output
__device__ float g_acc[(size_t)NN * DD];      // aggregation accumulator
__device__ float g_dout[RR * NN];             // out-degree counts
__device__ float g_din[RR * NN];              // in-degree counts
__device__ float g_rdout[RR * NN];
__device__ float g_rdin[RR * NN];
__device__ float g_w[(size_t)RR * EE];        // per-edge combined weight

// ---------------- small kernels --------------------------------------------

__global__ void zero_deg_kernel() {
    int i = blockIdx.x * blockDim.x + threadIdx.x;
    if (i < RR * NN) { g_dout[i] = 0.f; g_din[i] = 0.f; }
}

__global__ void zero_acc_kernel() {
    int i = blockIdx.x * blockDim.x + threadIdx.x;
    if (i < NN * DD / 4) ((float4*)g_acc)[i] = make_float4(0.f, 0.f, 0.f, 0.f);
}

__global__ void deg_kernel(const int* __restrict__ src, const int* __restrict__ dst) {
    long long i = (long long)blockIdx.x * blockDim.x + threadIdx.x;
    if (i >= (long long)RR * EE) return;
    int r = (int)(i / EE);
    atomicAdd(&g_dout[r * NN + src[i]], 1.f);
    atomicAdd(&g_din[r * NN + dst[i]], 1.f);
}

__global__ void rsqrt_kernel() {
    int i = blockIdx.x * blockDim.x + threadIdx.x;
    if (i >= RR * NN) return;
    g_rdout[i] = rsqrtf(fmaxf(g_dout[i], 1.f));
    g_rdin[i]  = rsqrtf(fmaxf(g_din[i], 1.f));
}

// w[e] = ew[e] * rsqrt(deg_out[src]) * rsqrt(deg_in[dst])  (same for both layers)
__global__ void edgew_kernel(const int* __restrict__ src, const int* __restrict__ dst,
                             const float* __restrict__ ew) {
    long long i = (long long)blockIdx.x * blockDim.x + threadIdx.x;
    if (i >= (long long)RR * EE) return;
    int r = (int)(i / EE);
    g_w[i] = ew[i] * g_rdout[r * NN + src[i]] * g_rdin[r * NN + dst[i]];
}

// ---------------- tf32x3 tensor-core GEMM: Y_r = h @ W_r --------------------
// Block: 64 rows x 128 cols, 256 threads (8 warps: 4 row-groups x 2 col-groups).
// K chunked by 16; operands split hi/lo (tf32) for fp32-level accuracy.
__global__ __launch_bounds__(256) void gemm_tf32_kernel(
    const float* __restrict__ h, const float* __restrict__ Wbase)
{
    __shared__ float sAh[64][20], sAl[64][20];
    __shared__ float sBh[16][132], sBl[16][132];

    const int r = blockIdx.y;
    const float* W = Wbase + (size_t)r * DD * DD;
    const int row0 = blockIdx.x * 64;
    const int tid = threadIdx.x;
    const int wid = tid >> 5;
    const int wr = wid & 3;          // row group (16 rows)
    const int wc = wid >> 2;         // col group (64 cols)

    wmma::fragment<wmma::accumulator, 16, 16, 8, float> acc[4];
#pragma unroll
    for (int i = 0; i < 4; i++) wmma::fill_fragment(acc[i], 0.f);

    for (int kc = 0; kc < DD; kc += 16) {
        // stage A chunk [64 x 16], hi/lo split
#pragma unroll
        for (int t = tid; t < 64 * 16; t += 256) {
            int rr = t >> 4, kk = t & 15;
            int n = row0 + rr;
            float a = (n < NN) ? h[(size_t)n * DD + kc + kk] : 0.f;
            float hi = wmma::__float_to_tf32(a);
            sAh[rr][kk] = hi;
            sAl[rr][kk] = wmma::__float_to_tf32(a - hi);
        }
        // stage B chunk [16 x 128], hi/lo split
#pragma unroll
        for (int t = tid; t < 16 * 128; t += 256) {
            int rr = t >> 7, j = t & 127;
            float b = W[(size_t)(kc + rr) * DD + j];
            float hi = wmma::__float_to_tf32(b);
            sBh[rr][j] = hi;
            sBl[rr][j] = wmma::__float_to_tf32(b - hi);
        }
        __syncthreads();

#pragma unroll
        for (int ks = 0; ks < 2; ks++) {
            wmma::fragment<wmma::matrix_a, 16, 16, 8, wmma::precision::tf32, wmma::row_major> ah, al;
            wmma::load_matrix_sync(ah, &sAh[wr * 16][ks * 8], 20);
            wmma::load_matrix_sync(al, &sAl[wr * 16][ks * 8], 20);
#pragma unroll
            for (int cg = 0; cg < 4; cg++) {
                int col = wc * 64 + cg * 16;
                wmma::fragment<wmma::matrix_b, 16, 16, 8, wmma::precision::tf32, wmma::row_major> bh, bl;
                wmma::load_matrix_sync(bh, &sBh[ks * 8][col], 132);
                wmma::load_matrix_sync(bl, &sBl[ks * 8][col], 132);
                wmma::mma_sync(acc[cg], ah, bh, acc[cg]);
                wmma::mma_sync(acc[cg], ah, bl, acc[cg]);
                wmma::mma_sync(acc[cg], al, bh, acc[cg]);
            }
        }
        __syncthreads();
    }

    float* out = g_Y + ((size_t)r * NP + row0 + wr * 16) * DD + wc * 64;
#pragma unroll
    for (int cg = 0; cg < 4; cg++)
        wmma::store_matrix_sync(out + cg * 16, acc[cg], DD, wmma::mem_row_major);
}

// ---------------- scatter: acc[dst] += Y_r[src] * w  (all relations) --------
__global__ __launch_bounds__(256) void scatter_kernel(
    const int* __restrict__ src, const int* __restrict__ dst)
{
    long long gid = (long long)blockIdx.x * blockDim.x + threadIdx.x;
    long long e = gid >> 5;
    int lane = (int)(gid & 31);
    if (e >= (long long)RR * EE) return;
    int r = (int)(e / EE);
    int s = src[e];
    int d = dst[e];
    float w = g_w[e];
    const float4 v = *(const float4*)(g_Y + ((size_t)r * NP + s) * DD + lane * 4);
    float* p = g_acc + (size_t)d * DD + lane * 4;
    asm volatile("red.global.add.v4.f32 [%0], {%1,%2,%3,%4};"
                 :: "l"(p), "f"(v.x * w), "f"(v.y * w), "f"(v.z * w), "f"(v.w * w)
                 : "memory");
}

// out[n][j] = relu(acc[n][j] + sum_r b[r][j])
__global__ void bias_relu_kernel(const float* __restrict__ b, float* __restrict__ out) {
    int i = blockIdx.x * blockDim.x + threadIdx.x;
    if (i >= NN * DD) return;
    int j = i & (DD - 1);
    float bs = b[j] + b[DD + j] + b[2 * DD + j] + b[3 * DD + j];
    out[i] = fmaxf(g_acc[i] + bs, 0.f);
}

// ---------------- launch ----------------------------------------------------

extern "C" void kernel_launch(void* const* d_in, const int* in_sizes, int n_in,
                              void* d_out, int out_size)
{
    const float* x   = (const float*)d_in[0];   // [N, D]
    const int*   src = (const int*)d_in[1];     // [R, E]
    const int*   dst = (const int*)d_in[2];     // [R, E]
    const float* ew  = (const float*)d_in[3];   // [R, E]
    const float* W1  = (const float*)d_in[4];   // [R, D, D]
    const float* b1  = (const float*)d_in[5];   // [R, D]
    const float* W2  = (const float*)d_in[6];   // [R, D, D]
    const float* b2  = (const float*)d_in[7];   // [R, D]
    float* out = (float*)d_out;

    const int T = 256;
    const long long RE = (long long)RR * EE;

    // degrees + per-edge weights (shared by both layers)
    zero_deg_kernel<<<(RR * NN + T - 1) / T, T>>>();
    deg_kernel<<<(int)((RE + T - 1) / T), T>>>(src, dst);
    rsqrt_kernel<<<(RR * NN + T - 1) / T, T>>>();
    edgew_kernel<<<(int)((RE + T - 1) / T), T>>>(src, dst, ew);

    dim3 ggrid(NP / 64, RR);
    const int scat_blocks = (int)((RE * 32 + T - 1) / T);
    const int elem_blocks = (NN * DD + T - 1) / T;
    const int zero_blocks = (NN * DD / 4 + T - 1) / T;

    // ---- layer 1 ----
    zero_acc_kernel<<<zero_blocks, T>>>();
    gemm_tf32_kernel<<<ggrid, T>>>(x, W1);
    scatter_kernel<<<scat_blocks, T>>>(src, dst);
    bias_relu_kernel<<<elem_blocks, T>>>(b1, g_h1);

    // ---- layer 2 ----
    zero_acc_kernel<<<zero_blocks, T>>>();
    gemm_tf32_kernel<<<ggrid, T>>>(g_h1, W2);
    scatter_kernel<<<scat_blocks, T>>>(src, dst);
    bias_relu_kernel<<<elem_blocks, T>>>(b2, out);
}

// round 3
// speedup vs baseline: 1.2047x; 1.1636x over previous
#include <cuda_runtime.h>
#include <mma.h>
#include <cstdint>

using namespace nvcuda;

#define NN 100000
#define NP 100032            // padded to multiple of 64
#define DD 128
#define EE 1600000
#define RR 4

#define SCAN_N   (RR * NN)          // 400000
#define SCAN_BLK 512
#define SCAN_NBLK ((SCAN_N + SCAN_BLK - 1) / SCAN_BLK)   // 782

// ---------------- device scratch (static: no allocations allowed) ----------
__device__ float g_Y[(size_t)RR * NP * DD];   // per-relation transformed feats
__device__ float g_h1[(size_t)NN * DD];       // layer-1 output
__device__ int   g_degout[SCAN_N];
__device__ int   g_degin[SCAN_N];
__device__ float g_rdout[SCAN_N];
__device__ float g_rdin[SCAN_N];
__device__ int   g_off[SCAN_N];               // CSR row offsets (flattened r*NN+n)
__device__ int   g_cur[SCAN_N];               // fill cursors
__device__ int   g_bsum[SCAN_NBLK];           // scan block sums
__device__ int   g_csr_src[(size_t)RR * EE];  // grouped-by-dst src ids
__device__ float g_csr_w[(size_t)RR * EE];    // per-edge combined weight

// ---------------- degree / weight prep --------------------------------------

__global__ void zero_deg_kernel() {
    int i = blockIdx.x * blockDim.x + threadIdx.x;
    if (i < SCAN_N) { g_degout[i] = 0; g_degin[i] = 0; }
}

__global__ void deg_kernel(const int* __restrict__ src, const int* __restrict__ dst) {
    long long i = (long long)blockIdx.x * blockDim.x + threadIdx.x;
    if (i >= (long long)RR * EE) return;
    int r = (int)(i / EE);
    atomicAdd(&g_degout[r * NN + src[i]], 1);
    atomicAdd(&g_degin[r * NN + dst[i]], 1);
}

__global__ void rsqrt_kernel() {
    int i = blockIdx.x * blockDim.x + threadIdx.x;
    if (i >= SCAN_N) return;
    g_rdout[i] = rsqrtf(fmaxf((float)g_degout[i], 1.f));
    g_rdin[i]  = rsqrtf(fmaxf((float)g_degin[i], 1.f));
}

// ---------------- exclusive scan of deg_in (3 kernels) -----------------------

__global__ void scan_a_kernel() {                 // per-block reduce
    __shared__ int s[SCAN_BLK];
    int i = blockIdx.x * SCAN_BLK + threadIdx.x;
    s[threadIdx.x] = (i < SCAN_N) ? g_degin[i] : 0;
    __syncthreads();
    for (int d = SCAN_BLK / 2; d > 0; d >>= 1) {
        if (threadIdx.x < d) s[threadIdx.x] += s[threadIdx.x + d];
        __syncthreads();
    }
    if (threadIdx.x == 0) g_bsum[blockIdx.x] = s[0];
}

__global__ void scan_b_kernel() {                 // scan block sums (1 block)
    __shared__ int s[1024];
    int t = threadIdx.x;
    s[t] = (t < SCAN_NBLK) ? g_bsum[t] : 0;
    __syncthreads();
    for (int d = 1; d < 1024; d <<= 1) {
        int v = (t >= d) ? s[t - d] : 0;
        __syncthreads();
        s[t] += v;
        __syncthreads();
    }
    if (t < SCAN_NBLK) g_bsum[t] = (t == 0) ? 0 : s[t - 1];   // exclusive
}

__global__ void scan_c_kernel() {                 // per-block scan + base
    __shared__ int s[SCAN_BLK];
    int i = blockIdx.x * SCAN_BLK + threadIdx.x;
    int v = (i < SCAN_N) ? g_degin[i] : 0;
    s[threadIdx.x] = v;
    __syncthreads();
    for (int d = 1; d < SCAN_BLK; d <<= 1) {
        int u = (threadIdx.x >= d) ? s[threadIdx.x - d] : 0;
        __syncthreads();
        s[threadIdx.x] += u;
        __syncthreads();
    }
    if (i < SCAN_N) {
        int ex = s[threadIdx.x] - v + g_bsum[blockIdx.x];     // exclusive
        g_off[i] = ex;
        g_cur[i] = ex;
    }
}

// ---------------- CSR fill ---------------------------------------------------

__global__ void fill_kernel(const int* __restrict__ src, const int* __restrict__ dst,
                            const float* __restrict__ ew) {
    long long i = (long long)blockIdx.x * blockDim.x + threadIdx.x;
    if (i >= (long long)RR * EE) return;
    int r = (int)(i / EE);
    int s = src[i], d = dst[i];
    float w = ew[i] * g_rdout[r * NN + s] * g_rdin[r * NN + d];
    int p = atomicAdd(&g_cur[r * NN + d], 1);
    g_csr_src[p] = s;
    g_csr_w[p] = w;
}

// ---------------- tf32x3 tensor-core GEMM: Y_r = h @ W_r --------------------
__global__ __launch_bounds__(256) void gemm_tf32_kernel(
    const float* __restrict__ h, const float* __restrict__ Wbase)
{
    __shared__ float sAh[64][20], sAl[64][20];
    __shared__ float sBh[16][132], sBl[16][132];

    const int r = blockIdx.y;
    const float* W = Wbase + (size_t)r * DD * DD;
    const int row0 = blockIdx.x * 64;
    const int tid = threadIdx.x;
    const int wid = tid >> 5;
    const int wr = wid & 3;
    const int wc = wid >> 2;

    wmma::fragment<wmma::accumulator, 16, 16, 8, float> acc[4];
#pragma unroll
    for (int i = 0; i < 4; i++) wmma::fill_fragment(acc[i], 0.f);

    for (int kc = 0; kc < DD; kc += 16) {
#pragma unroll
        for (int t = tid; t < 64 * 16; t += 256) {
            int rr = t >> 4, kk = t & 15;
            int n = row0 + rr;
            float a = (n < NN) ? h[(size_t)n * DD + kc + kk] : 0.f;
            float hi = wmma::__float_to_tf32(a);
            sAh[rr][kk] = hi;
            sAl[rr][kk] = wmma::__float_to_tf32(a - hi);
        }
#pragma unroll
        for (int t = tid; t < 16 * 128; t += 256) {
            int rr = t >> 7, j = t & 127;
            float b = W[(size_t)(kc + rr) * DD + j];
            float hi = wmma::__float_to_tf32(b);
            sBh[rr][j] = hi;
            sBl[rr][j] = wmma::__float_to_tf32(b - hi);
        }
        __syncthreads();

#pragma unroll
        for (int ks = 0; ks < 2; ks++) {
            wmma::fragment<wmma::matrix_a, 16, 16, 8, wmma::precision::tf32, wmma::row_major> ah, al;
            wmma::load_matrix_sync(ah, &sAh[wr * 16][ks * 8], 20);
            wmma::load_matrix_sync(al, &sAl[wr * 16][ks * 8], 20);
#pragma unroll
            for (int cg = 0; cg < 4; cg++) {
                int col = wc * 64 + cg * 16;
                wmma::fragment<wmma::matrix_b, 16, 16, 8, wmma::precision::tf32, wmma::row_major> bh, bl;
                wmma::load_matrix_sync(bh, &sBh[ks * 8][col], 132);
                wmma::load_matrix_sync(bl, &sBl[ks * 8][col], 132);
                wmma::mma_sync(acc[cg], ah, bh, acc[cg]);
                wmma::mma_sync(acc[cg], ah, bl, acc[cg]);
                wmma::mma_sync(acc[cg], al, bh, acc[cg]);
            }
        }
        __syncthreads();
    }

    float* out = g_Y + ((size_t)r * NP + row0 + wr * 16) * DD + wc * 64;
#pragma unroll
    for (int cg = 0; cg < 4; cg++)
        wmma::store_matrix_sync(out + cg * 16, acc[cg], DD, wmma::mem_row_major);
}

// ---------------- pull aggregation: out[n] = relu(sum_r sum_e Y_r[src]*w + bsum)
// One warp per node; lane owns 4 columns; fused bias + relu.
__global__ __launch_bounds__(256) void pull_kernel(
    const float* __restrict__ b, float* __restrict__ out)
{
    __shared__ float bsum[DD];
    if (threadIdx.x < DD)
        bsum[threadIdx.x] = b[threadIdx.x] + b[DD + threadIdx.x]
                          + b[2 * DD + threadIdx.x] + b[3 * DD + threadIdx.x];
    __syncthreads();

    int warp = (blockIdx.x * blockDim.x + threadIdx.x) >> 5;
    int lane = threadIdx.x & 31;
    if (warp >= NN) return;
    int n = warp;

    float4 a0 = make_float4(0.f, 0.f, 0.f, 0.f);
    float4 a1 = make_float4(0.f, 0.f, 0.f, 0.f);

#pragma unroll
    for (int r = 0; r < RR; r++) {
        int idx = r * NN + n;
        int start = g_off[idx];
        int cnt = g_degin[idx];
        const float* Yr = g_Y + (size_t)r * NP * DD;
        int j = start;
        for (; j + 1 < start + cnt; j += 2) {
            int s0 = g_csr_src[j];     float w0 = g_csr_w[j];
            int s1 = g_csr_src[j + 1]; float w1 = g_csr_w[j + 1];
            float4 v0 = *(const float4*)(Yr + (size_t)s0 * DD + lane * 4);
            float4 v1 = *(const float4*)(Yr + (size_t)s1 * DD + lane * 4);
            a0.x += v0.x * w0; a0.y += v0.y * w0; a0.z += v0.z * w0; a0.w += v0.w * w0;
            a1.x += v1.x * w1; a1.y += v1.y * w1; a1.z += v1.z * w1; a1.w += v1.w * w1;
        }
        if (j < start + cnt) {
            int s0 = g_csr_src[j]; float w0 = g_csr_w[j];
            float4 v0 = *(const float4*)(Yr + (size_t)s0 * DD + lane * 4);
            a0.x += v0.x * w0; a0.y += v0.y * w0; a0.z += v0.z * w0; a0.w += v0.w * w0;
        }
    }

    int c = lane * 4;
    float4 o;
    o.x = fmaxf(a0.x + a1.x + bsum[c],     0.f);
    o.y = fmaxf(a0.y + a1.y + bsum[c + 1], 0.f);
    o.z = fmaxf(a0.z + a1.z + bsum[c + 2], 0.f);
    o.w = fmaxf(a0.w + a1.w + bsum[c + 3], 0.f);
    *(float4*)(out + (size_t)n * DD + c) = o;
}

// ---------------- launch ----------------------------------------------------

extern "C" void kernel_launch(void* const* d_in, const int* in_sizes, int n_in,
                              void* d_out, int out_size)
{
    const float* x   = (const float*)d_in[0];
    const int*   src = (const int*)d_in[1];
    const int*   dst = (const int*)d_in[2];
    const float* ew  = (const float*)d_in[3];
    const float* W1  = (const float*)d_in[4];
    const float* b1  = (const float*)d_in[5];
    const float* W2  = (const float*)d_in[6];
    const float* b2  = (const float*)d_in[7];
    float* out = (float*)d_out;

    const int T = 256;
    const long long RE = (long long)RR * EE;
    const int edge_blocks = (int)((RE + T - 1) / T);

    // ---- setup (graph identical for both layers) ----
    zero_deg_kernel<<<(SCAN_N + T - 1) / T, T>>>();
    deg_kernel<<<edge_blocks, T>>>(src, dst);
    rsqrt_kernel<<<(SCAN_N + T - 1) / T, T>>>();
    scan_a_kernel<<<SCAN_NBLK, SCAN_BLK>>>();
    scan_b_kernel<<<1, 1024>>>();
    scan_c_kernel<<<SCAN_NBLK, SCAN_BLK>>>();
    fill_kernel<<<edge_blocks, T>>>(src, dst, ew);

    dim3 ggrid(NP / 64, RR);
    const int pull_blocks = (NN * 32 + T - 1) / T;   // warp per node

    // ---- layer 1 ----
    gemm_tf32_kernel<<<ggrid, T>>>(x, W1);
    pull_kernel<<<pull_blocks, T>>>(b1, g_h1);

    // ---- layer 2 ----
    gemm_tf32_kernel<<<ggrid, T>>>(g_h1, W2);
    pull_kernel<<<pull_blocks, T>>>(b2, out);
}

// round 4
// speedup vs baseline: 1.3268x; 1.1014x over previous
#include <cuda_runtime.h>
#include <mma.h>
#include <cstdint>

using namespace nvcuda;

#define NN 100000
#define NP 100032            // padded to multiple of 64
#define DD 128
#define EE 1600000
#define RR 4

#define SCAN_N   (RR * NN)          // 400000
#define SCAN_BLK 512
#define SCAN_NBLK ((SCAN_N + SCAN_BLK - 1) / SCAN_BLK)   // 782

// ---------------- device scratch (static: no allocations allowed) ----------
__device__ float  g_Ys[(size_t)NP * DD];       // single reused transformed buf
__device__ float  g_h1[(size_t)NN * DD];       // layer-1 output
__device__ float  g_acc[(size_t)NN * DD];      // aggregation accumulator
__device__ int    g_degout[SCAN_N];
__device__ int    g_degin[SCAN_N];
__device__ float  g_rdout[SCAN_N];
__device__ float  g_rdin[SCAN_N];
__device__ int    g_off[SCAN_N];               // CSR row offsets (r*NN+n)
__device__ int    g_cur[SCAN_N];
__device__ int    g_bsum[SCAN_NBLK];
__device__ float2 g_csr[(size_t)RR * EE];      // (src as int-bits, weight)

// ---------------- degree / weight prep --------------------------------------

__global__ void zero_deg_kernel() {
    int i = blockIdx.x * blockDim.x + threadIdx.x;
    if (i < SCAN_N) { g_degout[i] = 0; g_degin[i] = 0; }
}

__global__ void deg_kernel(const int* __restrict__ src, const int* __restrict__ dst) {
    long long i = (long long)blockIdx.x * blockDim.x + threadIdx.x;
    if (i >= (long long)RR * EE) return;
    int r = (int)(i / EE);
    atomicAdd(&g_degout[r * NN + src[i]], 1);
    atomicAdd(&g_degin[r * NN + dst[i]], 1);
}

__global__ void rsqrt_kernel() {
    int i = blockIdx.x * blockDim.x + threadIdx.x;
    if (i >= SCAN_N) return;
    g_rdout[i] = rsqrtf(fmaxf((float)g_degout[i], 1.f));
    g_rdin[i]  = rsqrtf(fmaxf((float)g_degin[i], 1.f));
}

// ---------------- exclusive scan of deg_in -----------------------------------

__global__ void scan_a_kernel() {
    __shared__ int s[SCAN_BLK];
    int i = blockIdx.x * SCAN_BLK + threadIdx.x;
    s[threadIdx.x] = (i < SCAN_N) ? g_degin[i] : 0;
    __syncthreads();
    for (int d = SCAN_BLK / 2; d > 0; d >>= 1) {
        if (threadIdx.x < d) s[threadIdx.x] += s[threadIdx.x + d];
        __syncthreads();
    }
    if (threadIdx.x == 0) g_bsum[blockIdx.x] = s[0];
}

__global__ void scan_b_kernel() {
    __shared__ int s[1024];
    int t = threadIdx.x;
    s[t] = (t < SCAN_NBLK) ? g_bsum[t] : 0;
    __syncthreads();
    for (int d = 1; d < 1024; d <<= 1) {
        int v = (t >= d) ? s[t - d] : 0;
        __syncthreads();
        s[t] += v;
        __syncthreads();
    }
    if (t < SCAN_NBLK) g_bsum[t] = (t == 0) ? 0 : s[t - 1];
}

__global__ void scan_c_kernel() {
    __shared__ int s[SCAN_BLK];
    int i = blockIdx.x * SCAN_BLK + threadIdx.x;
    int v = (i < SCAN_N) ? g_degin[i] : 0;
    s[threadIdx.x] = v;
    __syncthreads();
    for (int d = 1; d < SCAN_BLK; d <<= 1) {
        int u = (threadIdx.x >= d) ? s[threadIdx.x - d] : 0;
        __syncthreads();
        s[threadIdx.x] += u;
        __syncthreads();
    }
    if (i < SCAN_N) {
        int ex = s[threadIdx.x] - v + g_bsum[blockIdx.x];
        g_off[i] = ex;
        g_cur[i] = ex;
    }
}

// ---------------- CSR fill ---------------------------------------------------

__global__ void fill_kernel(const int* __restrict__ src, const int* __restrict__ dst,
                            const float* __restrict__ ew) {
    long long i = (long long)blockIdx.x * blockDim.x + threadIdx.x;
    if (i >= (long long)RR * EE) return;
    int r = (int)(i / EE);
    int s = src[i], d = dst[i];
    float w = ew[i] * g_rdout[r * NN + s] * g_rdin[r * NN + d];
    int p = atomicAdd(&g_cur[r * NN + d], 1);
    g_csr[p] = make_float2(__int_as_float(s), w);
}

// ---------------- tf32x3 tensor-core GEMM: Ys = h @ W ------------------------
__global__ __launch_bounds__(256) void gemm_tf32_kernel(
    const float* __restrict__ h, const float* __restrict__ W)
{
    __shared__ float sAh[64][20], sAl[64][20];
    __shared__ float sBh[16][132], sBl[16][132];

    const int row0 = blockIdx.x * 64;
    const int tid = threadIdx.x;
    const int wid = tid >> 5;
    const int wr = wid & 3;
    const int wc = wid >> 2;

    wmma::fragment<wmma::accumulator, 16, 16, 8, float> acc[4];
#pragma unroll
    for (int i = 0; i < 4; i++) wmma::fill_fragment(acc[i], 0.f);

    for (int kc = 0; kc < DD; kc += 16) {
#pragma unroll
        for (int t = tid; t < 64 * 16; t += 256) {
            int rr = t >> 4, kk = t & 15;
            int n = row0 + rr;
            float a = (n < NN) ? h[(size_t)n * DD + kc + kk] : 0.f;
            float hi = wmma::__float_to_tf32(a);
            sAh[rr][kk] = hi;
            sAl[rr][kk] = wmma::__float_to_tf32(a - hi);
        }
#pragma unroll
        for (int t = tid; t < 16 * 128; t += 256) {
            int rr = t >> 7, j = t & 127;
            float b = W[(size_t)(kc + rr) * DD + j];
            float hi = wmma::__float_to_tf32(b);
            sBh[rr][j] = hi;
            sBl[rr][j] = wmma::__float_to_tf32(b - hi);
        }
        __syncthreads();

#pragma unroll
        for (int ks = 0; ks < 2; ks++) {
            wmma::fragment<wmma::matrix_a, 16, 16, 8, wmma::precision::tf32, wmma::row_major> ah, al;
            wmma::load_matrix_sync(ah, &sAh[wr * 16][ks * 8], 20);
            wmma::load_matrix_sync(al, &sAl[wr * 16][ks * 8], 20);
#pragma unroll
            for (int cg = 0; cg < 4; cg++) {
                int col = wc * 64 + cg * 16;
                wmma::fragment<wmma::matrix_b, 16, 16, 8, wmma::precision::tf32, wmma::row_major> bh, bl;
                wmma::load_matrix_sync(bh, &sBh[ks * 8][col], 132);
                wmma::load_matrix_sync(bl, &sBl[ks * 8][col], 132);
                wmma::mma_sync(acc[cg], ah, bh, acc[cg]);
                wmma::mma_sync(acc[cg], ah, bl, acc[cg]);
                wmma::mma_sync(acc[cg], al, bh, acc[cg]);
            }
        }
        __syncthreads();
    }

    float* out = g_Ys + (size_t)(row0 + wr * 16) * DD + wc * 64;
#pragma unroll
    for (int cg = 0; cg < 4; cg++)
        wmma::store_matrix_sync(out + cg * 16, acc[cg], DD, wmma::mem_row_major);
}

// ---------------- per-relation pull: acc[n] (+)= sum_e Ys[src]*w -------------
// One warp per node; lane owns 4 cols; Ys + acc both L2-resident.
__global__ __launch_bounds__(256) void pull_r_kernel(int r, int first)
{
    int warp = (blockIdx.x * blockDim.x + threadIdx.x) >> 5;
    int lane = threadIdx.x & 31;
    if (warp >= NN) return;
    int idx = r * NN + warp;
    const float2* eb = g_csr + g_off[idx];
    int cnt = g_degin[idx];

    float4 a0 = make_float4(0.f, 0.f, 0.f, 0.f);
    float4 a1 = make_float4(0.f, 0.f, 0.f, 0.f);
    const int co = lane * 4;

    int j = 0;
    for (; j + 4 <= cnt; j += 4) {
        float2 e0 = eb[j],     e1 = eb[j + 1];
        float2 e2 = eb[j + 2], e3 = eb[j + 3];
        const float4 v0 = *(const float4*)(g_Ys + (size_t)__float_as_int(e0.x) * DD + co);
        const float4 v1 = *(const float4*)(g_Ys + (size_t)__float_as_int(e1.x) * DD + co);
        const float4 v2 = *(const float4*)(g_Ys + (size_t)__float_as_int(e2.x) * DD + co);
        const float4 v3 = *(const float4*)(g_Ys + (size_t)__float_as_int(e3.x) * DD + co);
        a0.x += v0.x * e0.y; a0.y += v0.y * e0.y; a0.z += v0.z * e0.y; a0.w += v0.w * e0.y;
        a1.x += v1.x * e1.y; a1.y += v1.y * e1.y; a1.z += v1.z * e1.y; a1.w += v1.w * e1.y;
        a0.x += v2.x * e2.y; a0.y += v2.y * e2.y; a0.z += v2.z * e2.y; a0.w += v2.w * e2.y;
        a1.x += v3.x * e3.y; a1.y += v3.y * e3.y; a1.z += v3.z * e3.y; a1.w += v3.w * e3.y;
    }
    for (; j < cnt; j++) {
        float2 e0 = eb[j];
        const float4 v0 = *(const float4*)(g_Ys + (size_t)__float_as_int(e0.x) * DD + co);
        a0.x += v0.x * e0.y; a0.y += v0.y * e0.y; a0.z += v0.z * e0.y; a0.w += v0.w * e0.y;
    }

    a0.x += a1.x; a0.y += a1.y; a0.z += a1.z; a0.w += a1.w;
    float* accp = g_acc + (size_t)warp * DD + co;
    if (!first) {
        float4 old = *(const float4*)accp;
        a0.x += old.x; a0.y += old.y; a0.z += old.z; a0.w += old.w;
    }
    *(float4*)accp = a0;
}

// out[n][j] = relu(acc[n][j] + sum_r b[r][j])
__global__ void bias_relu_kernel(const float* __restrict__ b, float* __restrict__ out) {
    int i = blockIdx.x * blockDim.x + threadIdx.x;
    if (i >= NN * DD) return;
    int j = i & (DD - 1);
    float bs = b[j] + b[DD + j] + b[2 * DD + j] + b[3 * DD + j];
    out[i] = fmaxf(g_acc[i] + bs, 0.f);
}

// ---------------- launch ----------------------------------------------------

extern "C" void kernel_launch(void* const* d_in, const int* in_sizes, int n_in,
                              void* d_out, int out_size)
{
    const float* x   = (const float*)d_in[0];
    const int*   src = (const int*)d_in[1];
    const int*   dst = (const int*)d_in[2];
    const float* ew  = (const float*)d_in[3];
    const float* W1  = (const float*)d_in[4];
    const float* b1  = (const float*)d_in[5];
    const float* W2  = (const float*)d_in[6];
    const float* b2  = (const float*)d_in[7];
    float* out = (float*)d_out;

    const int T = 256;
    const long long RE = (long long)RR * EE;
    const int edge_blocks = (int)((RE + T - 1) / T);

    // ---- setup (graph identical for both layers) ----
    zero_deg_kernel<<<(SCAN_N + T - 1) / T, T>>>();
    deg_kernel<<<edge_blocks, T>>>(src, dst);
    rsqrt_kernel<<<(SCAN_N + T - 1) / T, T>>>();
    scan_a_kernel<<<SCAN_NBLK, SCAN_BLK>>>();
    scan_b_kernel<<<1, 1024>>>();
    scan_c_kernel<<<SCAN_NBLK, SCAN_BLK>>>();
    fill_kernel<<<edge_blocks, T>>>(src, dst, ew);

    const int ggrid = NP / 64;
    const int pull_blocks = (NN * 32 + T - 1) / T;
    const int elem_blocks = (NN * DD + T - 1) / T;

    // ---- layer 1 ----
    for (int r = 0; r < RR; r++) {
        gemm_tf32_kernel<<<ggrid, T>>>(x, W1 + (size_t)r * DD * DD);
        pull_r_kernel<<<pull_blocks, T>>>(r, r == 0);
    }
    bias_relu_kernel<<<elem_blocks, T>>>(b1, g_h1);

    // ---- layer 2 ----
    for (int r = 0; r < RR; r++) {
        gemm_tf32_kernel<<<ggrid, T>>>(g_h1, W2 + (size_t)r * DD * DD);
        pull_r_kernel<<<pull_blocks, T>>>(r, r == 0);
    }
    bias_relu_kernel<<<elem_blocks, T>>>(b2, out);
}